// round 9
// baseline (speedup 1.0000x reference)
#include <cuda_runtime.h>
#include <cuda_fp16.h>

#define NU 8000
#define NI 4000
#define NN 12000
#define DD 64
#define NE 300000
#define WORDS 375          // ceil(12000/32)
#define WROW  376          // padded row stride in words
#define WPT   6            // 64 threads * 6 = 384 >= 376
#define CSTRIDE 128        // max unique neighbors per row (mean ~50, 11-sigma margin)

// Scratch (device globals only — referenced ONLY from device code)
__device__ unsigned g_adj[NN * WROW];       // 18 MB bitmask adjacency
__device__ int      g_csr[NN * CSTRIDE];    // 6.1 MB column indices
__device__ int      g_cnt[NN];
__device__ float    g_rdeg[NN];             // 1/max(deg,1)
__device__ float    g_sqdeg[NN];            // sqrt(max(deg,1))
// fp16 copies for gathering: one row = 64 halves = 128 B = 1 cache line
__device__ unsigned g_h0[NN * 32];          // half2-packed
__device__ unsigned g_h1[NN * 32];
__device__ unsigned g_h2[NN * 32];
// fp32 copies for the exact epilogue accumulation
__device__ float2   g_u0f[NN * 32];
__device__ float2   g_u1f[NN * 32];
__device__ float2   g_u2f[NN * 32];

__global__ void k_zero_adj() {
    int i = blockIdx.x * blockDim.x + threadIdx.x;
    const int n4 = NN * WROW / 4;           // 1,128,000 exactly
    if (i < n4) ((uint4*)g_adj)[i] = make_uint4(0u, 0u, 0u, 0u);
}

__global__ void k_set_edges(const int* __restrict__ ei) {
    int e = blockIdx.x * blockDim.x + threadIdx.x;
    if (e >= NE) return;
    int a = ei[e];
    int b = ei[NE + e];
    atomicOr(&g_adj[a * WROW + (b >> 5)], 1u << (b & 31));
    atomicOr(&g_adj[b * WROW + (a >> 5)], 1u << (a & 31));
}

// One 64-thread block per row: extract bitmask row -> CSR, degree scalars,
// and u0 = rsqrt(deg) * embed (fp32 + fp16 copies). Deterministic layout.
__global__ __launch_bounds__(64) void k_build(const float* __restrict__ ue,
                                              const float* __restrict__ ie) {
    int row = blockIdx.x;
    int t   = threadIdx.x;

    __shared__ int   s_wsum[2];
    __shared__ float s_dinv;

    const unsigned* __restrict__ arow = &g_adj[row * WROW];

    unsigned w[WPT];
    int c = 0;
    #pragma unroll
    for (int k = 0; k < WPT; k++) {
        int idx = t + 64 * k;                      // coalesced
        unsigned v = (idx < WORDS) ? arow[idx] : 0u;
        w[k] = v;
        c += __popc(v);
    }
    int lane = t & 31, wid = t >> 5;
    int sc = c;
    #pragma unroll
    for (int o = 1; o < 32; o <<= 1) {
        int n = __shfl_up_sync(0xffffffffu, sc, o);
        if (lane >= o) sc += n;
    }
    if (lane == 31) s_wsum[wid] = sc;
    __syncthreads();
    int base  = (sc - c) + (wid ? s_wsum[0] : 0);
    int total = s_wsum[0] + s_wsum[1];

    int* __restrict__ cr = &g_csr[row * CSTRIDE];
    #pragma unroll
    for (int k = 0; k < WPT; k++) {
        unsigned bits  = w[k];
        int      jbase = (t + 64 * k) * 32;
        while (bits) {
            int b = __ffs(bits) - 1;
            bits &= bits - 1;
            if (base < CSTRIDE) cr[base] = jbase + b;
            base++;
        }
    }

    if (t == 0) {
        float deg = fmaxf((float)total, 1.0f);
        g_cnt[row]   = (total < CSTRIDE) ? total : CSTRIDE;
        g_rdeg[row]  = 1.0f / deg;
        g_sqdeg[row] = sqrtf(deg);
        s_dinv       = rsqrtf(deg);
    }
    __syncthreads();

    float e = (row < NU) ? ue[row * DD + t] : ie[(row - NU) * DD + t];
    float v = e * s_dinv;
    ((float*)g_u0f)[row * DD + t] = v;
    ((__half*)g_h0)[row * DD + t] = __float2half_rn(v);
}

// SpMM on the transformed recursion: u_{l+1}[i] = rdeg[i] * sum_{j in N(i)} u_l[j].
// One warp per row; lane owns dims {2*lane, 2*lane+1} as half2 -> fp32 acc.
// Each neighbor gather = one 128B line. Indices broadcast via shfl.
__global__ __launch_bounds__(256) void k_spmm(int layer, float* __restrict__ dout) {
    const unsigned* __restrict__ hin =
        (layer == 0) ? g_h0 : (layer == 1) ? g_h1 : g_h2;
    unsigned* __restrict__ hout = (layer == 0) ? g_h1 : g_h2;
    float2*   __restrict__ fout = (layer == 0) ? g_u1f : g_u2f;

    int row  = (blockIdx.x * 256 + threadIdx.x) >> 5;   // grid covers NN exactly
    int lane = threadIdx.x & 31;

    int n = g_cnt[row];
    const int* __restrict__ cj = &g_csr[row * CSTRIDE];

    float ax = 0.0f, ay = 0.0f;
    int c = 0;
    for (; c + 32 <= n; c += 32) {
        int jv = cj[c + lane];                          // coalesced index load
        #pragma unroll
        for (int k = 0; k < 32; k++) {
            int j = __shfl_sync(0xffffffffu, jv, k);
            unsigned h = hin[j * 32 + lane];            // 128B line per warp
            float2 v = __half22float2(*(const half2*)&h);
            ax += v.x; ay += v.y;
        }
    }
    if (c < n) {
        int jv = cj[c + lane];                          // within CSTRIDE, safe
        int rem = n - c;
        for (int k = 0; k < rem; k++) {
            int j = __shfl_sync(0xffffffffu, jv, k);
            unsigned h = hin[j * 32 + lane];
            float2 v = __half22float2(*(const half2*)&h);
            ax += v.x; ay += v.y;
        }
    }

    float r = g_rdeg[row];
    float ux = ax * r, uy = ay * r;
    int o = row * 32 + lane;

    if (layer != 2) {
        half2 hh = __floats2half2_rn(ux, uy);
        hout[o] = *(const unsigned*)&hh;
        fout[o] = make_float2(ux, uy);
    } else {
        float2 a0 = g_u0f[o];
        float2 a1 = g_u1f[o];
        float2 a2 = g_u2f[o];
        float s = g_sqdeg[row] * 0.25f;
        float2 res;
        res.x = (a0.x + a1.x + a2.x + ux) * s;
        res.y = (a0.y + a1.y + a2.y + uy) * s;
        ((float2*)dout)[o] = res;
    }
}

extern "C" void kernel_launch(void* const* d_in, const int* in_sizes, int n_in,
                              void* d_out, int out_size) {
    const int*   ei = (const int*)  d_in[0];   // edge_index int32 (2, NE)
    const float* ue = (const float*)d_in[1];   // user_emb (8000, 64)
    const float* ie = (const float*)d_in[2];   // item_emb (4000, 64)
    float* out = (float*)d_out;

    k_zero_adj <<<(NN * WROW / 4 + 255) / 256, 256>>>();
    k_set_edges<<<(NE + 255) / 256, 256>>>(ei);
    k_build    <<<NN, 64>>>(ue, ie);

    // one warp per row: NN*32 threads / 256 = 1500 blocks (exact)
    k_spmm<<<NN * 32 / 256, 256>>>(0, nullptr);   // u0 -> u1
    k_spmm<<<NN * 32 / 256, 256>>>(1, nullptr);   // u1 -> u2
    k_spmm<<<NN * 32 / 256, 256>>>(2, out);       // u2 -> u3, fused final
}

// round 10
// speedup vs baseline: 1.0116x; 1.0116x over previous
#include <cuda_runtime.h>
#include <cuda_fp16.h>

#define NU 8000
#define NI 4000
#define NN 12000
#define DD 64
#define NE 300000
#define WORDS 375          // ceil(12000/32)
#define WROW  376          // padded row stride in words
#define WPT   6            // 64 threads * 6 = 384 >= 376
#define CSTRIDE 128        // max unique neighbors per row (mean ~50, 11-sigma margin)
#define ZROW  NN           // dummy neighbor: feature row NN is always all-zero

// Scratch (device globals only — referenced ONLY from device code)
__device__ unsigned g_adj[NN * WROW];       // 18 MB bitmask adjacency
__device__ int      g_csr[NN * CSTRIDE];    // 6.1 MB column indices (padded w/ ZROW)
__device__ int      g_cnt8[NN];             // neighbor count padded to multiple of 8
__device__ float    g_rdeg[NN];             // 1/max(deg,1)
__device__ float    g_sqdeg[NN];            // sqrt(max(deg,1))
// fp16 gather buffers: one row = 64 halves = 128 B = 1 cache line.
// Sized NN+1: row ZROW stays zero forever (.bss init, never written) -> deterministic.
__device__ unsigned g_h0[(NN + 1) * 32];    // half2-packed
__device__ unsigned g_h1[(NN + 1) * 32];
__device__ unsigned g_h2[(NN + 1) * 32];
// fp32 copies for the exact epilogue accumulation
__device__ float2   g_u0f[NN * 32];
__device__ float2   g_u1f[NN * 32];
__device__ float2   g_u2f[NN * 32];

__global__ void k_zero_adj() {
    int i = blockIdx.x * blockDim.x + threadIdx.x;
    const int n4 = NN * WROW / 4;           // 1,128,000 exactly
    if (i < n4) ((uint4*)g_adj)[i] = make_uint4(0u, 0u, 0u, 0u);
}

__global__ void k_set_edges(const int* __restrict__ ei) {
    int e = blockIdx.x * blockDim.x + threadIdx.x;
    if (e >= NE) return;
    int a = ei[e];
    int b = ei[NE + e];
    atomicOr(&g_adj[a * WROW + (b >> 5)], 1u << (b & 31));
    atomicOr(&g_adj[b * WROW + (a >> 5)], 1u << (a & 31));
}

// One 64-thread block per row: extract bitmask row -> CSR (padded to mult of 8
// with ZROW), degree scalars, u0 = rsqrt(deg)*embed (fp32+fp16). Deterministic.
__global__ __launch_bounds__(64) void k_build(const float* __restrict__ ue,
                                              const float* __restrict__ ie) {
    int row = blockIdx.x;
    int t   = threadIdx.x;

    __shared__ int   s_wsum[2];
    __shared__ float s_dinv;

    const unsigned* __restrict__ arow = &g_adj[row * WROW];

    unsigned w[WPT];
    int c = 0;
    #pragma unroll
    for (int k = 0; k < WPT; k++) {
        int idx = t + 64 * k;                      // coalesced
        unsigned v = (idx < WORDS) ? arow[idx] : 0u;
        w[k] = v;
        c += __popc(v);
    }
    int lane = t & 31, wid = t >> 5;
    int sc = c;
    #pragma unroll
    for (int o = 1; o < 32; o <<= 1) {
        int n = __shfl_up_sync(0xffffffffu, sc, o);
        if (lane >= o) sc += n;
    }
    if (lane == 31) s_wsum[wid] = sc;
    __syncthreads();
    int base  = (sc - c) + (wid ? s_wsum[0] : 0);
    int total = s_wsum[0] + s_wsum[1];

    int* __restrict__ cr = &g_csr[row * CSTRIDE];
    #pragma unroll
    for (int k = 0; k < WPT; k++) {
        unsigned bits  = w[k];
        int      jbase = (t + 64 * k) * 32;
        while (bits) {
            int b = __ffs(bits) - 1;
            bits &= bits - 1;
            if (base < CSTRIDE) cr[base] = jbase + b;
            base++;
        }
    }

    int nreal = (total < CSTRIDE) ? total : CSTRIDE;
    int n8 = (nreal + 7) & ~7;
    if (n8 > CSTRIDE) n8 = CSTRIDE;
    // pad [nreal, n8) with the zero row
    if (t < n8 - nreal) cr[nreal + t] = ZROW;

    if (t == 0) {
        float deg = fmaxf((float)total, 1.0f);
        g_cnt8[row]  = n8;
        g_rdeg[row]  = 1.0f / deg;
        g_sqdeg[row] = sqrtf(deg);
        s_dinv       = rsqrtf(deg);
    }
    __syncthreads();

    float e = (row < NU) ? ue[row * DD + t] : ie[(row - NU) * DD + t];
    float v = e * s_dinv;
    ((float*)g_u0f)[row * DD + t] = v;
    ((__half*)g_h0)[row * DD + t] = __float2half_rn(v);
}

// SpMM: u_{l+1}[i] = rdeg[i] * sum_{j in N(i)} u_l[j].
// One warp per row; lane owns dims {2*lane,2*lane+1} as half2 -> fp32 acc.
// Inner loop: explicit batches of 8 independent gathers (MLP=8), no remainder.
__global__ __launch_bounds__(256) void k_spmm(int layer, float* __restrict__ dout) {
    const unsigned* __restrict__ hin =
        (layer == 0) ? g_h0 : (layer == 1) ? g_h1 : g_h2;
    unsigned* __restrict__ hout = (layer == 0) ? g_h1 : g_h2;
    float2*   __restrict__ fout = (layer == 0) ? g_u1f : g_u2f;

    int row  = (blockIdx.x * 256 + threadIdx.x) >> 5;   // grid covers NN exactly
    int lane = threadIdx.x & 31;

    int n8 = g_cnt8[row];                               // multiple of 8
    const int* __restrict__ cj = &g_csr[row * CSTRIDE];
    const unsigned* __restrict__ hlane = hin + lane;

    float ax = 0.0f, ay = 0.0f;
    for (int c = 0; c < n8; c += 32) {
        int jv = cj[c + lane];              // coalesced; beyond n8 unused
        #pragma unroll
        for (int s = 0; s < 4; s++) {
            if (c + s * 8 >= n8) break;     // warp-uniform
            int ja[8];
            unsigned hv[8];
            #pragma unroll
            for (int k = 0; k < 8; k++)
                ja[k] = __shfl_sync(0xffffffffu, jv, s * 8 + k);
            #pragma unroll
            for (int k = 0; k < 8; k++)
                hv[k] = hlane[ja[k] * 32];  // 8 independent 128B-line gathers
            #pragma unroll
            for (int k = 0; k < 8; k++) {
                float2 v = __half22float2(*(const half2*)&hv[k]);
                ax += v.x; ay += v.y;
            }
        }
    }

    float r = g_rdeg[row];
    float ux = ax * r, uy = ay * r;
    int o = row * 32 + lane;

    if (layer != 2) {
        half2 hh = __floats2half2_rn(ux, uy);
        hout[o] = *(const unsigned*)&hh;
        fout[o] = make_float2(ux, uy);
    } else {
        float2 a0 = g_u0f[o];
        float2 a1 = g_u1f[o];
        float2 a2 = g_u2f[o];
        float s = g_sqdeg[row] * 0.25f;
        float2 res;
        res.x = (a0.x + a1.x + a2.x + ux) * s;
        res.y = (a0.y + a1.y + a2.y + uy) * s;
        ((float2*)dout)[o] = res;
    }
}

extern "C" void kernel_launch(void* const* d_in, const int* in_sizes, int n_in,
                              void* d_out, int out_size) {
    const int*   ei = (const int*)  d_in[0];   // edge_index int32 (2, NE)
    const float* ue = (const float*)d_in[1];   // user_emb (8000, 64)
    const float* ie = (const float*)d_in[2];   // item_emb (4000, 64)
    float* out = (float*)d_out;

    k_zero_adj <<<(NN * WROW / 4 + 255) / 256, 256>>>();
    k_set_edges<<<(NE + 255) / 256, 256>>>(ei);
    k_build    <<<NN, 64>>>(ue, ie);

    // one warp per row: NN*32 threads / 256 = 1500 blocks (exact)
    k_spmm<<<NN * 32 / 256, 256>>>(0, nullptr);   // u0 -> u1
    k_spmm<<<NN * 32 / 256, 256>>>(1, nullptr);   // u1 -> u2
    k_spmm<<<NN * 32 / 256, 256>>>(2, out);       // u2 -> u3, fused final
}

// round 12
// speedup vs baseline: 1.1775x; 1.1641x over previous
#include <cuda_runtime.h>
#include <cuda_fp16.h>

#define NU 8000
#define NI 4000
#define NN 12000
#define DD 64
#define NE 300000
#define WORDS 375          // ceil(12000/32)
#define WROW  376          // padded row stride in words
#define WPT   6            // 64 threads * 6 = 384 >= 376
#define CSTRIDE 128        // max unique neighbors per row (mean ~50, 11-sigma margin)
#define ZROW  NN           // dummy neighbor: feature row NN is always all-zero

// Scratch (device globals only — referenced ONLY from device code)
__device__ unsigned g_adj[NN * WROW];       // 18 MB bitmask adjacency
__device__ int      g_csr[NN * CSTRIDE];    // 6.1 MB column indices (padded w/ ZROW)
__device__ int      g_cnt8[NN];             // neighbor count padded to multiple of 8
__device__ float    g_rdeg[NN];             // 1/max(deg,1)
__device__ float    g_sqdeg[NN];            // sqrt(max(deg,1))
// fp16 gather buffers: one row = 64 halves = 128 B = 1 cache line = 8 uint4.
// Sized NN+1: row ZROW stays zero forever (.bss, never written) -> deterministic.
__device__ uint4    g_h0[(NN + 1) * 8];
__device__ uint4    g_h1[(NN + 1) * 8];
__device__ uint4    g_h2[(NN + 1) * 8];
// fp32 copies for the exact epilogue accumulation (float4-aligned)
__device__ float4   g_u0f[NN * 16];
__device__ float4   g_u1f[NN * 16];
__device__ float4   g_u2f[NN * 16];

static __device__ __forceinline__ half2 u2h(unsigned u) {
    half2 h; *(unsigned*)&h = u; return h;
}

__global__ void k_zero_adj() {
    int i = blockIdx.x * blockDim.x + threadIdx.x;
    const int n4 = NN * WROW / 4;           // 1,128,000 exactly
    if (i < n4) ((uint4*)g_adj)[i] = make_uint4(0u, 0u, 0u, 0u);
}

__global__ void k_set_edges(const int* __restrict__ ei) {
    int e = blockIdx.x * blockDim.x + threadIdx.x;
    if (e >= NE) return;
    int a = ei[e];
    int b = ei[NE + e];
    atomicOr(&g_adj[a * WROW + (b >> 5)], 1u << (b & 31));
    atomicOr(&g_adj[b * WROW + (a >> 5)], 1u << (a & 31));
}

// One 64-thread block per row: extract bitmask row -> CSR (padded to mult of 8
// with ZROW), degree scalars, u0 = rsqrt(deg)*embed (fp32+fp16). Deterministic.
__global__ __launch_bounds__(64) void k_build(const float* __restrict__ ue,
                                              const float* __restrict__ ie) {
    int row = blockIdx.x;
    int t   = threadIdx.x;

    __shared__ int   s_wsum[2];
    __shared__ float s_dinv;

    const unsigned* __restrict__ arow = &g_adj[row * WROW];

    unsigned w[WPT];
    int c = 0;
    #pragma unroll
    for (int k = 0; k < WPT; k++) {
        int idx = t + 64 * k;                      // coalesced
        unsigned v = (idx < WORDS) ? arow[idx] : 0u;
        w[k] = v;
        c += __popc(v);
    }
    int lane = t & 31, wid = t >> 5;
    int sc = c;
    #pragma unroll
    for (int o = 1; o < 32; o <<= 1) {
        int n = __shfl_up_sync(0xffffffffu, sc, o);
        if (lane >= o) sc += n;
    }
    if (lane == 31) s_wsum[wid] = sc;
    __syncthreads();
    int base  = (sc - c) + (wid ? s_wsum[0] : 0);
    int total = s_wsum[0] + s_wsum[1];

    int* __restrict__ cr = &g_csr[row * CSTRIDE];
    #pragma unroll
    for (int k = 0; k < WPT; k++) {
        unsigned bits  = w[k];
        int      jbase = (t + 64 * k) * 32;
        while (bits) {
            int b = __ffs(bits) - 1;
            bits &= bits - 1;
            if (base < CSTRIDE) cr[base] = jbase + b;
            base++;
        }
    }

    int nreal = (total < CSTRIDE) ? total : CSTRIDE;
    int n8 = (nreal + 7) & ~7;
    if (n8 > CSTRIDE) n8 = CSTRIDE;
    if (t < n8 - nreal) cr[nreal + t] = ZROW;      // pad with the zero row

    if (t == 0) {
        float deg = fmaxf((float)total, 1.0f);
        g_cnt8[row]  = n8;
        g_rdeg[row]  = 1.0f / deg;
        g_sqdeg[row] = sqrtf(deg);
        s_dinv       = rsqrtf(deg);
    }
    __syncthreads();

    float e = (row < NU) ? ue[row * DD + t] : ie[(row - NU) * DD + t];
    float v = e * s_dinv;
    ((float*)g_u0f)[row * DD + t] = v;
    ((__half*)g_h0)[row * DD + t] = __float2half_rn(v);
}

// SpMM: u_{l+1}[i] = rdeg[i] * sum_{j in N(i)} u_l[j].
// One warp per row. Lane layout: g = lane>>3 (neighbor slot 0..3 within a
// 4-neighbor step), sub = lane&7 (uint4 chunk = 8 dims of the 128B row).
// One LDG.128 per lane covers 4 neighbors per warp-load. Unroll 2 steps and
// pairwise-sum in fp16 (HADD2) before fp32 accumulation.
__global__ __launch_bounds__(256) void k_spmm(int layer, float* __restrict__ dout) {
    const uint4* __restrict__ hin =
        (layer == 0) ? g_h0 : (layer == 1) ? g_h1 : g_h2;
    uint4*  __restrict__ hout = (layer == 0) ? g_h1 : g_h2;
    float4* __restrict__ fout = (layer == 0) ? g_u1f : g_u2f;

    int row  = (blockIdx.x * 256 + threadIdx.x) >> 5;   // grid covers NN exactly
    int lane = threadIdx.x & 31;
    int g    = lane >> 3;
    int sub  = lane & 7;

    int n8 = g_cnt8[row];                               // multiple of 8
    const int* __restrict__ cj = &g_csr[row * CSTRIDE];

    float2 a0 = make_float2(0.f, 0.f), a1 = a0, a2 = a0, a3 = a0;

    for (int c = 0; c < n8; c += 32) {
        int jv = cj[c + lane];              // coalesced; unused slots never selected
        int m = n8 - c; if (m > 32) m = 32; // multiple of 8 -> (m>>2) even
        for (int s = 0; s < (m >> 2); s += 2) {
            int j0 = __shfl_sync(0xffffffffu, jv, s * 4 + g);
            int j1 = __shfl_sync(0xffffffffu, jv, s * 4 + 4 + g);
            uint4 v0 = hin[j0 * 8 + sub];   // two independent 128B warp-loads
            uint4 v1 = hin[j1 * 8 + sub];
            half2 p0 = __hadd2(u2h(v0.x), u2h(v1.x));
            half2 p1 = __hadd2(u2h(v0.y), u2h(v1.y));
            half2 p2 = __hadd2(u2h(v0.z), u2h(v1.z));
            half2 p3 = __hadd2(u2h(v0.w), u2h(v1.w));
            float2 f0 = __half22float2(p0);
            float2 f1 = __half22float2(p1);
            float2 f2 = __half22float2(p2);
            float2 f3 = __half22float2(p3);
            a0.x += f0.x; a0.y += f0.y;
            a1.x += f1.x; a1.y += f1.y;
            a2.x += f2.x; a2.y += f2.y;
            a3.x += f3.x; a3.y += f3.y;
        }
    }

    // reduce across the 4 neighbor lane-groups (lanes xor 8, xor 16 share dims)
    #pragma unroll
    for (int o = 8; o <= 16; o <<= 1) {
        a0.x += __shfl_xor_sync(0xffffffffu, a0.x, o);
        a0.y += __shfl_xor_sync(0xffffffffu, a0.y, o);
        a1.x += __shfl_xor_sync(0xffffffffu, a1.x, o);
        a1.y += __shfl_xor_sync(0xffffffffu, a1.y, o);
        a2.x += __shfl_xor_sync(0xffffffffu, a2.x, o);
        a2.y += __shfl_xor_sync(0xffffffffu, a2.y, o);
        a3.x += __shfl_xor_sync(0xffffffffu, a3.x, o);
        a3.y += __shfl_xor_sync(0xffffffffu, a3.y, o);
    }

    if (g == 0) {                           // lanes 0..7 own dims sub*8..sub*8+7
        float r = g_rdeg[row];
        float u0 = a0.x * r, u1 = a0.y * r, u2 = a1.x * r, u3 = a1.y * r;
        float u4 = a2.x * r, u5 = a2.y * r, u6 = a3.x * r, u7 = a3.y * r;
        int ob = row * 8 + sub;             // uint4 index
        int fb = row * 16 + sub * 2;        // float4 index

        if (layer != 2) {
            uint4 hp;
            half2 h0 = __floats2half2_rn(u0, u1);
            half2 h1 = __floats2half2_rn(u2, u3);
            half2 h2 = __floats2half2_rn(u4, u5);
            half2 h3 = __floats2half2_rn(u6, u7);
            hp.x = *(unsigned*)&h0; hp.y = *(unsigned*)&h1;
            hp.z = *(unsigned*)&h2; hp.w = *(unsigned*)&h3;
            hout[ob] = hp;
            fout[fb]     = make_float4(u0, u1, u2, u3);
            fout[fb + 1] = make_float4(u4, u5, u6, u7);
        } else {
            float4 b0 = g_u0f[fb],     c0 = g_u1f[fb],     d0 = g_u2f[fb];
            float4 b1 = g_u0f[fb + 1], c1 = g_u1f[fb + 1], d1 = g_u2f[fb + 1];
            float s = g_sqdeg[row] * 0.25f;
            float4 r0, r1;
            r0.x = (b0.x + c0.x + d0.x + u0) * s;
            r0.y = (b0.y + c0.y + d0.y + u1) * s;
            r0.z = (b0.z + c0.z + d0.z + u2) * s;
            r0.w = (b0.w + c0.w + d0.w + u3) * s;
            r1.x = (b1.x + c1.x + d1.x + u4) * s;
            r1.y = (b1.y + c1.y + d1.y + u5) * s;
            r1.z = (b1.z + c1.z + d1.z + u6) * s;
            r1.w = (b1.w + c1.w + d1.w + u7) * s;
            ((float4*)dout)[fb]     = r0;
            ((float4*)dout)[fb + 1] = r1;
        }
    }
}

extern "C" void kernel_launch(void* const* d_in, const int* in_sizes, int n_in,
                              void* d_out, int out_size) {
    const int*   ei = (const int*)  d_in[0];   // edge_index int32 (2, NE)
    const float* ue = (const float*)d_in[1];   // user_emb (8000, 64)
    const float* ie = (const float*)d_in[2];   // item_emb (4000, 64)
    float* out = (float*)d_out;

    k_zero_adj <<<(NN * WROW / 4 + 255) / 256, 256>>>();
    k_set_edges<<<(NE + 255) / 256, 256>>>(ei);
    k_build    <<<NN, 64>>>(ue, ie);

    // one warp per row: NN*32 threads / 256 = 1500 blocks (exact)
    k_spmm<<<NN * 32 / 256, 256>>>(0, nullptr);   // u0 -> u1
    k_spmm<<<NN * 32 / 256, 256>>>(1, nullptr);   // u1 -> u2
    k_spmm<<<NN * 32 / 256, 256>>>(2, out);       // u2 -> u3, fused final
}

// round 13
// speedup vs baseline: 1.1799x; 1.0020x over previous
#include <cuda_runtime.h>
#include <cuda_fp16.h>

#define NU 8000
#define NI 4000
#define NN 12000
#define DD 64
#define NE 300000
#define WORDS 375          // ceil(12000/32)
#define WROW  376          // padded row stride in words
#define WPT   6            // 64 threads * 6 = 384 >= 376
#define CSTRIDE 128        // max unique neighbors per row (mean ~50, 11-sigma margin)
#define ZROW  NN           // dummy neighbor: feature row NN is always all-zero

// Scratch (device globals only — referenced ONLY from device code)
__device__ unsigned g_adj[NN * WROW];       // 18 MB bitmask adjacency
__device__ int      g_csr[NN * CSTRIDE];    // 6.1 MB column indices (padded w/ ZROW)
__device__ int      g_cnt16[NN];            // neighbor count padded to multiple of 16
__device__ float    g_rdeg[NN];             // 1/max(deg,1)
__device__ float    g_sqdeg[NN];            // sqrt(max(deg,1))
// fp16 gather buffers: one row = 64 halves = 128 B = 1 cache line = 8 uint4.
// Sized NN+1: row ZROW stays zero forever (.bss, never written) -> deterministic.
__device__ uint4    g_h0[(NN + 1) * 8];
__device__ uint4    g_h1[(NN + 1) * 8];
__device__ uint4    g_h2[(NN + 1) * 8];
// fp32 copies for the exact epilogue accumulation (float4-aligned)
__device__ float4   g_u0f[NN * 16];
__device__ float4   g_u1f[NN * 16];
__device__ float4   g_u2f[NN * 16];

static __device__ __forceinline__ half2 u2h(unsigned u) {
    half2 h; *(unsigned*)&h = u; return h;
}

__global__ void k_zero_adj() {
    int i = blockIdx.x * blockDim.x + threadIdx.x;
    const int n4 = NN * WROW / 4;           // 1,128,000 exactly
    if (i < n4) ((uint4*)g_adj)[i] = make_uint4(0u, 0u, 0u, 0u);
}

__global__ void k_set_edges(const int* __restrict__ ei) {
    int e = blockIdx.x * blockDim.x + threadIdx.x;
    if (e >= NE) return;
    int a = ei[e];
    int b = ei[NE + e];
    atomicOr(&g_adj[a * WROW + (b >> 5)], 1u << (b & 31));
    atomicOr(&g_adj[b * WROW + (a >> 5)], 1u << (a & 31));
}

// One 64-thread block per row: extract bitmask row -> CSR (padded to mult of 16
// with ZROW), degree scalars, u0 = rsqrt(deg)*embed (fp32+fp16). Deterministic.
__global__ __launch_bounds__(64) void k_build(const float* __restrict__ ue,
                                              const float* __restrict__ ie) {
    int row = blockIdx.x;
    int t   = threadIdx.x;

    __shared__ int   s_wsum[2];
    __shared__ float s_dinv;

    const unsigned* __restrict__ arow = &g_adj[row * WROW];

    unsigned w[WPT];
    int c = 0;
    #pragma unroll
    for (int k = 0; k < WPT; k++) {
        int idx = t + 64 * k;                      // coalesced
        unsigned v = (idx < WORDS) ? arow[idx] : 0u;
        w[k] = v;
        c += __popc(v);
    }
    int lane = t & 31, wid = t >> 5;
    int sc = c;
    #pragma unroll
    for (int o = 1; o < 32; o <<= 1) {
        int n = __shfl_up_sync(0xffffffffu, sc, o);
        if (lane >= o) sc += n;
    }
    if (lane == 31) s_wsum[wid] = sc;
    __syncthreads();
    int base  = (sc - c) + (wid ? s_wsum[0] : 0);
    int total = s_wsum[0] + s_wsum[1];

    int* __restrict__ cr = &g_csr[row * CSTRIDE];
    #pragma unroll
    for (int k = 0; k < WPT; k++) {
        unsigned bits  = w[k];
        int      jbase = (t + 64 * k) * 32;
        while (bits) {
            int b = __ffs(bits) - 1;
            bits &= bits - 1;
            if (base < CSTRIDE) cr[base] = jbase + b;
            base++;
        }
    }

    int nreal = (total < CSTRIDE) ? total : CSTRIDE;
    int n16 = (nreal + 15) & ~15;
    if (n16 > CSTRIDE) n16 = CSTRIDE;
    if (t < n16 - nreal) cr[nreal + t] = ZROW;     // pad with the zero row

    if (t == 0) {
        float deg = fmaxf((float)total, 1.0f);
        g_cnt16[row] = n16;
        g_rdeg[row]  = 1.0f / deg;
        g_sqdeg[row] = sqrtf(deg);
        s_dinv       = rsqrtf(deg);
    }
    __syncthreads();

    float e = (row < NU) ? ue[row * DD + t] : ie[(row - NU) * DD + t];
    float v = e * s_dinv;
    ((float*)g_u0f)[row * DD + t] = v;
    ((__half*)g_h0)[row * DD + t] = __float2half_rn(v);
}

// SpMM: u_{l+1}[i] = rdeg[i] * sum_{j in N(i)} u_l[j].
// One warp per row. Lane layout: g = lane>>3 (neighbor slot within a 4-batch),
// sub = lane&7 (uint4 chunk = 8 dims of the 128B row). Each 16-neighbor step
// issues 4 independent LDG.128 per lane (MLP=4); fp16 pairwise add, fp32 acc.
__global__ __launch_bounds__(256) void k_spmm(int layer, float* __restrict__ dout) {
    const uint4* __restrict__ hin =
        (layer == 0) ? g_h0 : (layer == 1) ? g_h1 : g_h2;
    uint4*  __restrict__ hout = (layer == 0) ? g_h1 : g_h2;
    float4* __restrict__ fout = (layer == 0) ? g_u1f : g_u2f;

    int row  = (blockIdx.x * 256 + threadIdx.x) >> 5;   // grid covers NN exactly
    int lane = threadIdx.x & 31;
    int g    = lane >> 3;
    int sub  = lane & 7;

    int n16 = g_cnt16[row];                             // multiple of 16
    const int* __restrict__ cj = &g_csr[row * CSTRIDE];
    const uint4* __restrict__ hsub = hin + sub;

    float2 a0 = make_float2(0.f, 0.f), a1 = a0, a2 = a0, a3 = a0;

    for (int c = 0; c < n16; c += 32) {
        int jv = cj[c + lane];              // one coalesced index load per 32
        // ---- first 16 neighbors: 4 independent 128B warp-loads ----
        {
            int j0 = __shfl_sync(0xffffffffu, jv,  0 + g);
            int j1 = __shfl_sync(0xffffffffu, jv,  4 + g);
            int j2 = __shfl_sync(0xffffffffu, jv,  8 + g);
            int j3 = __shfl_sync(0xffffffffu, jv, 12 + g);
            uint4 v0 = hsub[j0 * 8];
            uint4 v1 = hsub[j1 * 8];
            uint4 v2 = hsub[j2 * 8];
            uint4 v3 = hsub[j3 * 8];
            half2 p0 = __hadd2(u2h(v0.x), u2h(v1.x));
            half2 p1 = __hadd2(u2h(v0.y), u2h(v1.y));
            half2 p2 = __hadd2(u2h(v0.z), u2h(v1.z));
            half2 p3 = __hadd2(u2h(v0.w), u2h(v1.w));
            half2 q0 = __hadd2(u2h(v2.x), u2h(v3.x));
            half2 q1 = __hadd2(u2h(v2.y), u2h(v3.y));
            half2 q2 = __hadd2(u2h(v2.z), u2h(v3.z));
            half2 q3 = __hadd2(u2h(v2.w), u2h(v3.w));
            float2 f; 
            f = __half22float2(p0); a0.x += f.x; a0.y += f.y;
            f = __half22float2(q0); a0.x += f.x; a0.y += f.y;
            f = __half22float2(p1); a1.x += f.x; a1.y += f.y;
            f = __half22float2(q1); a1.x += f.x; a1.y += f.y;
            f = __half22float2(p2); a2.x += f.x; a2.y += f.y;
            f = __half22float2(q2); a2.x += f.x; a2.y += f.y;
            f = __half22float2(p3); a3.x += f.x; a3.y += f.y;
            f = __half22float2(q3); a3.x += f.x; a3.y += f.y;
        }
        // ---- second 16 neighbors of this chunk (warp-uniform guard) ----
        if (c + 16 < n16) {
            int j0 = __shfl_sync(0xffffffffu, jv, 16 + g);
            int j1 = __shfl_sync(0xffffffffu, jv, 20 + g);
            int j2 = __shfl_sync(0xffffffffu, jv, 24 + g);
            int j3 = __shfl_sync(0xffffffffu, jv, 28 + g);
            uint4 v0 = hsub[j0 * 8];
            uint4 v1 = hsub[j1 * 8];
            uint4 v2 = hsub[j2 * 8];
            uint4 v3 = hsub[j3 * 8];
            half2 p0 = __hadd2(u2h(v0.x), u2h(v1.x));
            half2 p1 = __hadd2(u2h(v0.y), u2h(v1.y));
            half2 p2 = __hadd2(u2h(v0.z), u2h(v1.z));
            half2 p3 = __hadd2(u2h(v0.w), u2h(v1.w));
            half2 q0 = __hadd2(u2h(v2.x), u2h(v3.x));
            half2 q1 = __hadd2(u2h(v2.y), u2h(v3.y));
            half2 q2 = __hadd2(u2h(v2.z), u2h(v3.z));
            half2 q3 = __hadd2(u2h(v2.w), u2h(v3.w));
            float2 f;
            f = __half22float2(p0); a0.x += f.x; a0.y += f.y;
            f = __half22float2(q0); a0.x += f.x; a0.y += f.y;
            f = __half22float2(p1); a1.x += f.x; a1.y += f.y;
            f = __half22float2(q1); a1.x += f.x; a1.y += f.y;
            f = __half22float2(p2); a2.x += f.x; a2.y += f.y;
            f = __half22float2(q2); a2.x += f.x; a2.y += f.y;
            f = __half22float2(p3); a3.x += f.x; a3.y += f.y;
            f = __half22float2(q3); a3.x += f.x; a3.y += f.y;
        }
    }

    // reduce across the 4 neighbor lane-groups (lanes xor 8, xor 16 share dims)
    #pragma unroll
    for (int o = 8; o <= 16; o <<= 1) {
        a0.x += __shfl_xor_sync(0xffffffffu, a0.x, o);
        a0.y += __shfl_xor_sync(0xffffffffu, a0.y, o);
        a1.x += __shfl_xor_sync(0xffffffffu, a1.x, o);
        a1.y += __shfl_xor_sync(0xffffffffu, a1.y, o);
        a2.x += __shfl_xor_sync(0xffffffffu, a2.x, o);
        a2.y += __shfl_xor_sync(0xffffffffu, a2.y, o);
        a3.x += __shfl_xor_sync(0xffffffffu, a3.x, o);
        a3.y += __shfl_xor_sync(0xffffffffu, a3.y, o);
    }

    if (g == 0) {                           // lanes 0..7 own dims sub*8..sub*8+7
        float r = g_rdeg[row];
        float u0 = a0.x * r, u1 = a0.y * r, u2 = a1.x * r, u3 = a1.y * r;
        float u4 = a2.x * r, u5 = a2.y * r, u6 = a3.x * r, u7 = a3.y * r;
        int ob = row * 8 + sub;             // uint4 index
        int fb = row * 16 + sub * 2;        // float4 index

        if (layer != 2) {
            uint4 hp;
            half2 h0 = __floats2half2_rn(u0, u1);
            half2 h1 = __floats2half2_rn(u2, u3);
            half2 h2 = __floats2half2_rn(u4, u5);
            half2 h3 = __floats2half2_rn(u6, u7);
            hp.x = *(unsigned*)&h0; hp.y = *(unsigned*)&h1;
            hp.z = *(unsigned*)&h2; hp.w = *(unsigned*)&h3;
            hout[ob] = hp;
            fout[fb]     = make_float4(u0, u1, u2, u3);
            fout[fb + 1] = make_float4(u4, u5, u6, u7);
        } else {
            float4 b0 = g_u0f[fb],     c0 = g_u1f[fb],     d0 = g_u2f[fb];
            float4 b1 = g_u0f[fb + 1], c1 = g_u1f[fb + 1], d1 = g_u2f[fb + 1];
            float s = g_sqdeg[row] * 0.25f;
            float4 r0, r1;
            r0.x = (b0.x + c0.x + d0.x + u0) * s;
            r0.y = (b0.y + c0.y + d0.y + u1) * s;
            r0.z = (b0.z + c0.z + d0.z + u2) * s;
            r0.w = (b0.w + c0.w + d0.w + u3) * s;
            r1.x = (b1.x + c1.x + d1.x + u4) * s;
            r1.y = (b1.y + c1.y + d1.y + u5) * s;
            r1.z = (b1.z + c1.z + d1.z + u6) * s;
            r1.w = (b1.w + c1.w + d1.w + u7) * s;
            ((float4*)dout)[fb]     = r0;
            ((float4*)dout)[fb + 1] = r1;
        }
    }
}

extern "C" void kernel_launch(void* const* d_in, const int* in_sizes, int n_in,
                              void* d_out, int out_size) {
    const int*   ei = (const int*)  d_in[0];   // edge_index int32 (2, NE)
    const float* ue = (const float*)d_in[1];   // user_emb (8000, 64)
    const float* ie = (const float*)d_in[2];   // item_emb (4000, 64)
    float* out = (float*)d_out;

    k_zero_adj <<<(NN * WROW / 4 + 255) / 256, 256>>>();
    k_set_edges<<<(NE + 255) / 256, 256>>>(ei);
    k_build    <<<NN, 64>>>(ue, ie);

    // one warp per row: NN*32 threads / 256 = 1500 blocks (exact)
    k_spmm<<<NN * 32 / 256, 256>>>(0, nullptr);   // u0 -> u1
    k_spmm<<<NN * 32 / 256, 256>>>(1, nullptr);   // u1 -> u2
    k_spmm<<<NN * 32 / 256, 256>>>(2, out);       // u2 -> u3, fused final
}